// round 5
// baseline (speedup 1.0000x reference)
#include <cuda_runtime.h>
#include <cstdint>

#define SQ   2048
#define HID  2560
#define NH   16
#define NKV  4
#define HD   128
#define QKV_DIM (NH*HD + 2*NKV*HD)   // 3072
#define EPS  1e-6f
#define ATT_SCALE 0.08838834764831845f  // 1/sqrt(128)
#define VOFF (NH*HD + NKV*HD)

// ---------------- scratch (device globals, no allocation) ----------------
__device__ float g_qkv[(size_t)SQ * QKV_DIM];
__device__ float g_scores[(size_t)NH * SQ * SQ];
__device__ float g_att[(size_t)SQ * NH * HD];
__device__ float g_hs_r[(size_t)SQ * HID];
__device__ float g_wqkv_r[(size_t)QKV_DIM * HID];
__device__ float g_wo_r[(size_t)HID * NH * HD];
__device__ float g_vt[(size_t)NKV * HD * SQ];

__device__ __forceinline__ uint32_t f2tf32(float x) {
    uint32_t u;
    asm("cvt.rna.tf32.f32 %0, %1;" : "=r"(u) : "f"(x));
    return u;
}
__device__ __forceinline__ float roundtf(float x) { return __uint_as_float(f2tf32(x)); }

__device__ __forceinline__ void mma_tf32(float* d, const uint32_t* a, const uint32_t* b) {
    asm volatile(
        "mma.sync.aligned.m16n8k8.row.col.f32.tf32.tf32.f32 "
        "{%0,%1,%2,%3}, {%4,%5,%6,%7}, {%8,%9}, {%0,%1,%2,%3};\n"
        : "+f"(d[0]), "+f"(d[1]), "+f"(d[2]), "+f"(d[3])
        : "r"(a[0]), "r"(a[1]), "r"(a[2]), "r"(a[3]), "r"(b[0]), "r"(b[1]));
}

// ---------------- tf32 tensor-core GEMM, 3-stage cp.async, 64x64 warp tiles ----------------
// C[m,n] = alpha * sum_k A[m,k] * B[n,k]   (both row-major, NT)
// Operands must already be tf32-rounded fp32.
// CAUSAL : skip N-tiles with bx > by.  CAUSALK: bound K at (by+1)*128.
// ROUND  : round output to tf32.
// 128x128 CTA tile, 128 threads (4 warps, 2x2 of 64x64), K chunks of 32.
template<bool CAUSAL, bool CAUSALK, bool ROUND>
__global__ void __launch_bounds__(128, 2) mma_gemm(
    const float* __restrict__ A, const float* __restrict__ B, float* __restrict__ C,
    int K, int lda, int ldb, int ldc,
    long long aBatch, long long bBatch, int bDiv, long long cBatch, float alpha)
{
    const int bx = blockIdx.x, by = blockIdx.y, bz = blockIdx.z;
    if (CAUSAL && bx > by) return;

    A += (long long)bz * aBatch;
    B += (long long)(bz / bDiv) * bBatch;
    C += (long long)bz * cBatch;

    extern __shared__ float4 dynsmem[];
    float4 (*As)[128][8] = (float4 (*)[128][8])(dynsmem);            // [3][128][8]
    float4 (*Bs)[128][8] = (float4 (*)[128][8])(dynsmem + 3*128*8);  // [3][128][8]

    const int t    = threadIdx.x;
    const int lane = t & 31, wid = t >> 5;
    const int wm   = (wid & 1) * 64;
    const int wn   = (wid >> 1) * 64;
    const int m0   = by * 128, n0 = bx * 128;
    const int grp  = lane >> 2, tid4 = lane & 3;

    // loader: thread t -> A row t (8 chunks) + B row t (8 chunks)
    const int x7 = t & 7;
    const float* Aptr = A + (long long)(m0 + t) * lda;
    const float* Bptr = B + (long long)(n0 + t) * ldb;

    float acc[4][8][4];
    #pragma unroll
    for (int i = 0; i < 4; i++)
        #pragma unroll
        for (int j = 0; j < 8; j++)
            #pragma unroll
            for (int r = 0; r < 4; r++) acc[i][j][r] = 0.f;

    const int Kfull = CAUSALK ? (((by + 1) * 128 < K) ? (by + 1) * 128 : K) : K;
    const int nK = Kfull >> 5;

    auto issue = [&](int st, int k0) {
        #pragma unroll
        for (int c = 0; c < 8; c++) {
            uint32_t da = (uint32_t)__cvta_generic_to_shared(&As[st][t][c ^ x7]);
            asm volatile("cp.async.cg.shared.global [%0], [%1], 16;\n"
                         :: "r"(da), "l"(Aptr + k0 + c * 4));
        }
        #pragma unroll
        for (int c = 0; c < 8; c++) {
            uint32_t db = (uint32_t)__cvta_generic_to_shared(&Bs[st][t][c ^ x7]);
            asm volatile("cp.async.cg.shared.global [%0], [%1], 16;\n"
                         :: "r"(db), "l"(Bptr + k0 + c * 4));
        }
    };

    // preload stages 0,1 (nK >= 4 always here)
    issue(0, 0);
    asm volatile("cp.async.commit_group;\n");
    issue(1, 32);
    asm volatile("cp.async.commit_group;\n");

    for (int kt = 0; kt < nK; kt++) {
        asm volatile("cp.async.wait_group 1;\n");
        __syncthreads();

        const int st = kt % 3;
        const uint32_t* Aw = (const uint32_t*)(As + st);
        const uint32_t* Bw = (const uint32_t*)(Bs + st);

        #pragma unroll
        for (int j = 0; j < 4; j++) {
            const int c0 = ((2 * j)     ^ grp) * 4 + tid4;
            const int c1 = ((2 * j + 1) ^ grp) * 4 + tid4;
            uint32_t af[4][4], bf[8][2];
            #pragma unroll
            for (int mt = 0; mt < 4; mt++) {
                const int m = wm + mt * 16 + grp;
                af[mt][0] = Aw[m * 32 + c0];
                af[mt][1] = Aw[(m + 8) * 32 + c0];
                af[mt][2] = Aw[m * 32 + c1];
                af[mt][3] = Aw[(m + 8) * 32 + c1];
            }
            #pragma unroll
            for (int nt = 0; nt < 8; nt++) {
                const int nn = wn + nt * 8 + grp;
                bf[nt][0] = Bw[nn * 32 + c0];
                bf[nt][1] = Bw[nn * 32 + c1];
            }
            #pragma unroll
            for (int mt = 0; mt < 4; mt++)
                #pragma unroll
                for (int nt = 0; nt < 8; nt++)
                    mma_tf32(acc[mt][nt], af[mt], bf[nt]);
        }

        // issue chunk kt+2 into stage (kt+2)%3 — safe: barrier above ensured
        // everyone finished compute(kt-1), which is the last reader of that stage.
        if (kt + 2 < nK) issue((kt + 2) % 3, (kt + 2) << 5);
        asm volatile("cp.async.commit_group;\n");
    }

    #pragma unroll
    for (int mt = 0; mt < 4; mt++) {
        #pragma unroll
        for (int nt = 0; nt < 8; nt++) {
            const int r0 = m0 + wm + mt * 16 + grp;
            const int col = n0 + wn + nt * 8 + tid4 * 2;
            float2 lo, hi;
            lo.x = acc[mt][nt][0] * alpha; lo.y = acc[mt][nt][1] * alpha;
            hi.x = acc[mt][nt][2] * alpha; hi.y = acc[mt][nt][3] * alpha;
            if (ROUND) {
                lo.x = roundtf(lo.x); lo.y = roundtf(lo.y);
                hi.x = roundtf(hi.x); hi.y = roundtf(hi.y);
            }
            *(float2*)(C + (long long)r0 * ldc + col)       = lo;
            *(float2*)(C + (long long)(r0 + 8) * ldc + col) = hi;
        }
    }
}

// ---------------- tf32 round-copy ----------------
__global__ void __launch_bounds__(256) round_copy(const float* __restrict__ src,
                                                 float* __restrict__ dst, int n4)
{
    int i = blockIdx.x * 256 + threadIdx.x;
    if (i < n4) {
        float4 v = ((const float4*)src)[i];
        v.x = roundtf(v.x); v.y = roundtf(v.y);
        v.z = roundtf(v.z); v.w = roundtf(v.w);
        ((float4*)dst)[i] = v;
    }
}

// ---------------- V transpose ----------------
__global__ void __launch_bounds__(256) vt_kernel()
{
    __shared__ float tile[32][33];
    const int s0 = blockIdx.x * 32, d0 = blockIdx.y * 32;
    const int tx = threadIdx.x & 31, ty = threadIdx.x >> 5;
    #pragma unroll
    for (int r = ty; r < 32; r += 8)
        tile[r][tx] = g_qkv[(long long)(s0 + r) * QKV_DIM + VOFF + d0 + tx];
    __syncthreads();
    #pragma unroll
    for (int r = ty; r < 32; r += 8)
        g_vt[(long long)(d0 + r) * SQ + s0 + tx] = tile[tx][r];
}

// ---------------- fused RMSNorm + RoPE ----------------
__global__ void __launch_bounds__(128) norm_rope_kernel(
    const float* __restrict__ qw, const float* __restrict__ kw,
    const float* __restrict__ cosT, const float* __restrict__ sinT,
    const int* __restrict__ positions)
{
    const int tok = blockIdx.x;
    const int hh  = blockIdx.y;
    const int d   = threadIdx.x;

    float* ptr;
    const float* w;
    if (hh < NH) { ptr = g_qkv + (long long)tok * QKV_DIM + hh * HD;            w = qw; }
    else         { ptr = g_qkv + (long long)tok * QKV_DIM + NH*HD + (hh-NH)*HD; w = kw; }

    __shared__ float x[HD];
    __shared__ float red[4];

    float v = ptr[d];
    float ss = v * v;
    #pragma unroll
    for (int o = 16; o > 0; o >>= 1) ss += __shfl_xor_sync(0xffffffffu, ss, o);
    if ((d & 31) == 0) red[d >> 5] = ss;
    __syncthreads();
    float tot = red[0] + red[1] + red[2] + red[3];
    float r = rsqrtf(tot * (1.0f / HD) + EPS);
    x[d] = v * r * w[d];
    __syncthreads();

    const int pos = positions[tok];
    const int p = d >> 1;
    const float c = cosT[pos * (HD/2) + p];
    const float s = sinT[pos * (HD/2) + p];
    float out;
    if ((d & 1) == 0) out = x[d] * c - x[d + 1] * s;
    else              out = x[d - 1] * s + x[d] * c;
    ptr[d] = roundtf(out);
}

// ---------------- single-pass causal softmax ----------------
__global__ void __launch_bounds__(256) softmax_kernel()
{
    const int q = blockIdx.x, h = blockIdx.y;
    float* row = g_scores + ((long long)h * SQ + q) * SQ;
    const int n = q + 1;
    const int lim = ((q >> 7) + 1) << 7;
    const int nv = lim >> 2;
    const int t = threadIdx.x;

    __shared__ float red[8];

    float4 v[2];
    float mx = -1e30f;
    #pragma unroll
    for (int i = 0; i < 2; i++) {
        const int idx = t + i * 256;
        if (idx < nv) {
            float4 u = ((const float4*)row)[idx];
            const int k = idx * 4;
            u.x = (k + 0 < n) ? u.x : -1e30f;
            u.y = (k + 1 < n) ? u.y : -1e30f;
            u.z = (k + 2 < n) ? u.z : -1e30f;
            u.w = (k + 3 < n) ? u.w : -1e30f;
            mx = fmaxf(mx, fmaxf(fmaxf(u.x, u.y), fmaxf(u.z, u.w)));
            v[i] = u;
        }
    }
    #pragma unroll
    for (int o = 16; o > 0; o >>= 1) mx = fmaxf(mx, __shfl_xor_sync(0xffffffffu, mx, o));
    if ((t & 31) == 0) red[t >> 5] = mx;
    __syncthreads();
    mx = red[0];
    #pragma unroll
    for (int i = 1; i < 8; i++) mx = fmaxf(mx, red[i]);

    float sum = 0.f;
    #pragma unroll
    for (int i = 0; i < 2; i++) {
        const int idx = t + i * 256;
        if (idx < nv) {
            float4 u = v[i];
            u.x = __expf(u.x - mx); u.y = __expf(u.y - mx);
            u.z = __expf(u.z - mx); u.w = __expf(u.w - mx);
            sum += (u.x + u.y) + (u.z + u.w);
            v[i] = u;
        }
    }
    __syncthreads();
    #pragma unroll
    for (int o = 16; o > 0; o >>= 1) sum += __shfl_xor_sync(0xffffffffu, sum, o);
    if ((t & 31) == 0) red[t >> 5] = sum;
    __syncthreads();
    sum = red[0] + red[1] + red[2] + red[3] + red[4] + red[5] + red[6] + red[7];
    const float inv = 1.0f / sum;

    #pragma unroll
    for (int i = 0; i < 2; i++) {
        const int idx = t + i * 256;
        if (idx < nv) {
            float4 u = v[i];
            u.x = roundtf(u.x * inv); u.y = roundtf(u.y * inv);
            u.z = roundtf(u.z * inv); u.w = roundtf(u.w * inv);
            ((float4*)row)[idx] = u;
        }
    }
}

// ---------------- launch ----------------
extern "C" void kernel_launch(void* const* d_in, const int* in_sizes, int n_in,
                              void* d_out, int out_size)
{
    const float* hs     = (const float*)d_in[0];
    const float* w_qkv  = (const float*)d_in[1];
    const float* w_o    = (const float*)d_in[2];
    const float* qnw    = (const float*)d_in[3];
    const float* knw    = (const float*)d_in[4];
    const float* cosT   = (const float*)d_in[5];
    const float* sinT   = (const float*)d_in[6];
    const int* positions = (const int*)d_in[9];
    float* out = (float*)d_out;

    float *qkv, *scores, *att, *hs_r, *wqkv_r, *wo_r, *vt;
    cudaGetSymbolAddress((void**)&qkv,    g_qkv);
    cudaGetSymbolAddress((void**)&scores, g_scores);
    cudaGetSymbolAddress((void**)&att,    g_att);
    cudaGetSymbolAddress((void**)&hs_r,   g_hs_r);
    cudaGetSymbolAddress((void**)&wqkv_r, g_wqkv_r);
    cudaGetSymbolAddress((void**)&wo_r,   g_wo_r);
    cudaGetSymbolAddress((void**)&vt,     g_vt);

    const int SMEM = 3 * 2 * 128 * 8 * 16;  // 96 KB (3 stages x (A+B) x 16KB)
    cudaFuncSetAttribute(mma_gemm<false, false, true >, cudaFuncAttributeMaxDynamicSharedMemorySize, SMEM);
    cudaFuncSetAttribute(mma_gemm<true,  false, false>, cudaFuncAttributeMaxDynamicSharedMemorySize, SMEM);
    cudaFuncSetAttribute(mma_gemm<false, true,  true >, cudaFuncAttributeMaxDynamicSharedMemorySize, SMEM);
    cudaFuncSetAttribute(mma_gemm<false, false, false>, cudaFuncAttributeMaxDynamicSharedMemorySize, SMEM);

    // 0) tf32-round raw operands
    round_copy<<<(SQ*HID/4 + 255)/256, 256>>>(hs, hs_r, SQ*HID/4);
    round_copy<<<(QKV_DIM*HID/4 + 255)/256, 256>>>(w_qkv, wqkv_r, QKV_DIM*HID/4);
    round_copy<<<(HID*NH*HD/4 + 255)/256, 256>>>(w_o, wo_r, HID*NH*HD/4);

    // 1) QKV projection
    mma_gemm<false, false, true><<<dim3(QKV_DIM/128, SQ/128, 1), 128, SMEM>>>(
        hs_r, wqkv_r, qkv, HID, HID, HID, QKV_DIM, 0, 0, 1, 0, 1.0f);

    // 2) RMSNorm + RoPE in-place
    norm_rope_kernel<<<dim3(SQ, NH + NKV), 128>>>(qnw, knw, cosT, sinT, positions);

    // 3) V transpose
    vt_kernel<<<dim3(SQ/32, NKV*HD/32), 256>>>();

    // 4) scores = Q @ K^T * SCALE (causal tile skip)
    mma_gemm<true, false, false><<<dim3(SQ/128, SQ/128, NH), 128, SMEM>>>(
        qkv, qkv + NH*HD, scores, HD, QKV_DIM, QKV_DIM, SQ,
        HD, HD, NH/NKV, (long long)SQ * SQ, ATT_SCALE);

    // 5) causal softmax
    softmax_kernel<<<dim3(SQ, NH), 256>>>();

    // 6) att = P @ V (causal-K bound)
    mma_gemm<false, true, true><<<dim3(HD/128, SQ/128, NH), 128, SMEM>>>(
        scores, vt, att, SQ, SQ, SQ, NH*HD,
        (long long)SQ * SQ, (long long)HD * SQ, NH/NKV, HD, 1.0f);

    // 7) output projection
    mma_gemm<false, false, false><<<dim3(HID/128, SQ/128, 1), 128, SMEM>>>(
        att, wo_r, out, NH*HD, NH*HD, NH*HD, HID, 0, 0, 1, 0, 1.0f);
}

// round 6
// speedup vs baseline: 1.5232x; 1.5232x over previous
#include <cuda_runtime.h>
#include <cstdint>

#define SQ   2048
#define HID  2560
#define NH   16
#define NKV  4
#define HD   128
#define QKV_DIM (NH*HD + 2*NKV*HD)   // 3072
#define EPS  1e-6f
#define ATT_SCALE 0.08838834764831845f  // 1/sqrt(128)
#define VOFF (NH*HD + NKV*HD)

// ---------------- scratch (device globals, no allocation) ----------------
__device__ float g_qkv[(size_t)SQ * QKV_DIM];
__device__ float g_scores[(size_t)NH * SQ * SQ];
__device__ float g_att[(size_t)SQ * NH * HD];
__device__ float g_hs_r[(size_t)SQ * HID];
__device__ float g_wqkv_r[(size_t)QKV_DIM * HID];
__device__ float g_wo_r[(size_t)HID * NH * HD];
__device__ float g_vt[(size_t)NKV * HD * SQ];

__device__ __forceinline__ uint32_t f2tf32(float x) {
    uint32_t u;
    asm("cvt.rna.tf32.f32 %0, %1;" : "=r"(u) : "f"(x));
    return u;
}
__device__ __forceinline__ float roundtf(float x) { return __uint_as_float(f2tf32(x)); }

__device__ __forceinline__ void mma_tf32(float* d, const uint32_t* a, const uint32_t* b) {
    asm volatile(
        "mma.sync.aligned.m16n8k8.row.col.f32.tf32.tf32.f32 "
        "{%0,%1,%2,%3}, {%4,%5,%6,%7}, {%8,%9}, {%0,%1,%2,%3};\n"
        : "+f"(d[0]), "+f"(d[1]), "+f"(d[2]), "+f"(d[3])
        : "r"(a[0]), "r"(a[1]), "r"(a[2]), "r"(a[3]), "r"(b[0]), "r"(b[1]));
}

__device__ __forceinline__ void ldmx4(uint32_t* r, uint32_t addr) {
    asm volatile("ldmatrix.sync.aligned.m8n8.x4.shared.b16 {%0,%1,%2,%3}, [%4];"
        : "=r"(r[0]), "=r"(r[1]), "=r"(r[2]), "=r"(r[3]) : "r"(addr));
}

// ---------------- tf32 tensor-core GEMM ----------------
// C[m,n] = alpha * sum_k A[m,k] * B[n,k]   (both row-major, NT)
// Operands must already be tf32-rounded fp32.
// 128x128 CTA tile, 256 threads (8 warps, 2Mx4N of 64x32), K chunks of 32,
// 3-stage cp.async pipeline, ldmatrix fragment loads.
// SMEM rows: [row 128][8 float4], granule swizzle c^(row&7).
template<bool CAUSAL, bool CAUSALK, bool ROUND>
__global__ void __launch_bounds__(256, 2) mma_gemm(
    const float* __restrict__ A, const float* __restrict__ B, float* __restrict__ C,
    int K, int lda, int ldb, int ldc,
    long long aBatch, long long bBatch, int bDiv, long long cBatch, float alpha)
{
    const int bx = blockIdx.x, by = blockIdx.y, bz = blockIdx.z;
    if (CAUSAL && bx > by) return;

    A += (long long)bz * aBatch;
    B += (long long)(bz / bDiv) * bBatch;
    C += (long long)bz * cBatch;

    extern __shared__ float4 dynsmem[];
    // layout: A stages [3][128][8], then B stages [3][128][8]
    const uint32_t sbase = (uint32_t)__cvta_generic_to_shared(dynsmem);

    const int t    = threadIdx.x;
    const int lane = t & 31, wid = t >> 5;
    const int wm   = (wid & 1) * 64;
    const int wn   = (wid >> 1) * 32;
    const int m0   = by * 128, n0 = bx * 128;
    const int grp  = lane >> 2, tid4 = lane & 3;

    // ldmatrix thread->address mapping
    const int l8    = lane & 7;
    const int aoff8 = ((lane >> 3) & 1) * 8;   // A: matrix row offset
    const int ags   = (lane >> 4) & 1;         // A: granule select
    const int boff8 = ((lane >> 4) & 1) * 8;   // B: matrix row offset
    const int bgs   = (lane >> 3) & 1;         // B: granule select
    // byte offsets of fragment rows within a stage (row*128)
    uint32_t arow[4], brow[2];
    #pragma unroll
    for (int mt = 0; mt < 4; mt++) arow[mt] = (uint32_t)(wm + mt * 16 + aoff8 + l8) * 128u;
    #pragma unroll
    for (int pr = 0; pr < 2; pr++) brow[pr] = (uint32_t)(wn + pr * 16 + boff8 + l8) * 128u;

    // loader: thread t -> row t>>1, 4 granules starting at (t&1)*4
    const int lrow = t >> 1;
    const int cb   = (t & 1) * 4;
    const int x7   = lrow & 7;
    const float* Aptr = A + (long long)(m0 + lrow) * lda;
    const float* Bptr = B + (long long)(n0 + lrow) * ldb;

    float acc[4][4][4];
    #pragma unroll
    for (int i = 0; i < 4; i++)
        #pragma unroll
        for (int j = 0; j < 4; j++)
            #pragma unroll
            for (int r = 0; r < 4; r++) acc[i][j][r] = 0.f;

    const int Kfull = CAUSALK ? (((by + 1) * 128 < K) ? (by + 1) * 128 : K) : K;
    const int nK = Kfull >> 5;

    auto issue = [&](int st, int k0) {
        const uint32_t ab = sbase + st * 16384u + (uint32_t)lrow * 128u;
        const uint32_t bb = sbase + 49152u + st * 16384u + (uint32_t)lrow * 128u;
        #pragma unroll
        for (int c = 0; c < 4; c++) {
            uint32_t da = ab + (uint32_t)(((cb + c) ^ x7) << 4);
            asm volatile("cp.async.cg.shared.global [%0], [%1], 16;\n"
                         :: "r"(da), "l"(Aptr + k0 + (cb + c) * 4));
        }
        #pragma unroll
        for (int c = 0; c < 4; c++) {
            uint32_t db = bb + (uint32_t)(((cb + c) ^ x7) << 4);
            asm volatile("cp.async.cg.shared.global [%0], [%1], 16;\n"
                         :: "r"(db), "l"(Bptr + k0 + (cb + c) * 4));
        }
    };

    // preload 2 stages (nK >= 4 for all uses)
    issue(0, 0);
    asm volatile("cp.async.commit_group;\n");
    issue(1, 32);
    asm volatile("cp.async.commit_group;\n");

    for (int kt = 0; kt < nK; kt++) {
        asm volatile("cp.async.wait_group 1;\n");
        __syncthreads();

        const int st = kt - (kt / 3) * 3;
        const uint32_t sA = sbase + st * 16384u;
        const uint32_t sB = sbase + 49152u + st * 16384u;

        #pragma unroll
        for (int j = 0; j < 4; j++) {
            const uint32_t ga = (uint32_t)(((2 * j + ags) ^ l8) << 4);
            const uint32_t gb = (uint32_t)(((2 * j + bgs) ^ l8) << 4);
            uint32_t af[4][4], bq[2][4];
            #pragma unroll
            for (int mt = 0; mt < 4; mt++) ldmx4(af[mt], sA + arow[mt] + ga);
            ldmx4(bq[0], sB + brow[0] + gb);
            ldmx4(bq[1], sB + brow[1] + gb);
            #pragma unroll
            for (int mt = 0; mt < 4; mt++) {
                mma_tf32(acc[mt][0], af[mt], &bq[0][0]);
                mma_tf32(acc[mt][1], af[mt], &bq[0][2]);
                mma_tf32(acc[mt][2], af[mt], &bq[1][0]);
                mma_tf32(acc[mt][3], af[mt], &bq[1][2]);
            }
        }

        // safe: barrier above guarantees all finished compute(kt-1),
        // the last reader of stage (kt+2)%3.
        if (kt + 2 < nK) issue((kt + 2) - ((kt + 2) / 3) * 3, (kt + 2) << 5);
        asm volatile("cp.async.commit_group;\n");
    }

    #pragma unroll
    for (int mt = 0; mt < 4; mt++) {
        #pragma unroll
        for (int nt = 0; nt < 4; nt++) {
            const int r0 = m0 + wm + mt * 16 + grp;
            const int col = n0 + wn + nt * 8 + tid4 * 2;
            float2 lo, hi;
            lo.x = acc[mt][nt][0] * alpha; lo.y = acc[mt][nt][1] * alpha;
            hi.x = acc[mt][nt][2] * alpha; hi.y = acc[mt][nt][3] * alpha;
            if (ROUND) {
                lo.x = roundtf(lo.x); lo.y = roundtf(lo.y);
                hi.x = roundtf(hi.x); hi.y = roundtf(hi.y);
            }
            *(float2*)(C + (long long)r0 * ldc + col)       = lo;
            *(float2*)(C + (long long)(r0 + 8) * ldc + col) = hi;
        }
    }
}

// ---------------- tf32 round-copy ----------------
__global__ void __launch_bounds__(256) round_copy(const float* __restrict__ src,
                                                 float* __restrict__ dst, int n4)
{
    int i = blockIdx.x * 256 + threadIdx.x;
    if (i < n4) {
        float4 v = ((const float4*)src)[i];
        v.x = roundtf(v.x); v.y = roundtf(v.y);
        v.z = roundtf(v.z); v.w = roundtf(v.w);
        ((float4*)dst)[i] = v;
    }
}

// ---------------- V transpose ----------------
__global__ void __launch_bounds__(256) vt_kernel()
{
    __shared__ float tile[32][33];
    const int s0 = blockIdx.x * 32, d0 = blockIdx.y * 32;
    const int tx = threadIdx.x & 31, ty = threadIdx.x >> 5;
    #pragma unroll
    for (int r = ty; r < 32; r += 8)
        tile[r][tx] = g_qkv[(long long)(s0 + r) * QKV_DIM + VOFF + d0 + tx];
    __syncthreads();
    #pragma unroll
    for (int r = ty; r < 32; r += 8)
        g_vt[(long long)(d0 + r) * SQ + s0 + tx] = tile[tx][r];
}

// ---------------- fused RMSNorm + RoPE ----------------
__global__ void __launch_bounds__(128) norm_rope_kernel(
    const float* __restrict__ qw, const float* __restrict__ kw,
    const float* __restrict__ cosT, const float* __restrict__ sinT,
    const int* __restrict__ positions)
{
    const int tok = blockIdx.x;
    const int hh  = blockIdx.y;
    const int d   = threadIdx.x;

    float* ptr;
    const float* w;
    if (hh < NH) { ptr = g_qkv + (long long)tok * QKV_DIM + hh * HD;            w = qw; }
    else         { ptr = g_qkv + (long long)tok * QKV_DIM + NH*HD + (hh-NH)*HD; w = kw; }

    __shared__ float x[HD];
    __shared__ float red[4];

    float v = ptr[d];
    float ss = v * v;
    #pragma unroll
    for (int o = 16; o > 0; o >>= 1) ss += __shfl_xor_sync(0xffffffffu, ss, o);
    if ((d & 31) == 0) red[d >> 5] = ss;
    __syncthreads();
    float tot = red[0] + red[1] + red[2] + red[3];
    float r = rsqrtf(tot * (1.0f / HD) + EPS);
    x[d] = v * r * w[d];
    __syncthreads();

    const int pos = positions[tok];
    const int p = d >> 1;
    const float c = cosT[pos * (HD/2) + p];
    const float s = sinT[pos * (HD/2) + p];
    float out;
    if ((d & 1) == 0) out = x[d] * c - x[d + 1] * s;
    else              out = x[d - 1] * s + x[d] * c;
    ptr[d] = roundtf(out);
}

// ---------------- single-pass causal softmax ----------------
__global__ void __launch_bounds__(256) softmax_kernel()
{
    const int q = blockIdx.x, h = blockIdx.y;
    float* row = g_scores + ((long long)h * SQ + q) * SQ;
    const int n = q + 1;
    const int lim = ((q >> 7) + 1) << 7;
    const int nv = lim >> 2;
    const int t = threadIdx.x;

    __shared__ float red[8];

    float4 v[2];
    float mx = -1e30f;
    #pragma unroll
    for (int i = 0; i < 2; i++) {
        const int idx = t + i * 256;
        if (idx < nv) {
            float4 u = ((const float4*)row)[idx];
            const int k = idx * 4;
            u.x = (k + 0 < n) ? u.x : -1e30f;
            u.y = (k + 1 < n) ? u.y : -1e30f;
            u.z = (k + 2 < n) ? u.z : -1e30f;
            u.w = (k + 3 < n) ? u.w : -1e30f;
            mx = fmaxf(mx, fmaxf(fmaxf(u.x, u.y), fmaxf(u.z, u.w)));
            v[i] = u;
        }
    }
    #pragma unroll
    for (int o = 16; o > 0; o >>= 1) mx = fmaxf(mx, __shfl_xor_sync(0xffffffffu, mx, o));
    if ((t & 31) == 0) red[t >> 5] = mx;
    __syncthreads();
    mx = red[0];
    #pragma unroll
    for (int i = 1; i < 8; i++) mx = fmaxf(mx, red[i]);

    float sum = 0.f;
    #pragma unroll
    for (int i = 0; i < 2; i++) {
        const int idx = t + i * 256;
        if (idx < nv) {
            float4 u = v[i];
            u.x = __expf(u.x - mx); u.y = __expf(u.y - mx);
            u.z = __expf(u.z - mx); u.w = __expf(u.w - mx);
            sum += (u.x + u.y) + (u.z + u.w);
            v[i] = u;
        }
    }
    __syncthreads();
    #pragma unroll
    for (int o = 16; o > 0; o >>= 1) sum += __shfl_xor_sync(0xffffffffu, sum, o);
    if ((t & 31) == 0) red[t >> 5] = sum;
    __syncthreads();
    sum = red[0] + red[1] + red[2] + red[3] + red[4] + red[5] + red[6] + red[7];
    const float inv = 1.0f / sum;

    #pragma unroll
    for (int i = 0; i < 2; i++) {
        const int idx = t + i * 256;
        if (idx < nv) {
            float4 u = v[i];
            u.x = roundtf(u.x * inv); u.y = roundtf(u.y * inv);
            u.z = roundtf(u.z * inv); u.w = roundtf(u.w * inv);
            ((float4*)row)[idx] = u;
        }
    }
}

// ---------------- launch ----------------
extern "C" void kernel_launch(void* const* d_in, const int* in_sizes, int n_in,
                              void* d_out, int out_size)
{
    const float* hs     = (const float*)d_in[0];
    const float* w_qkv  = (const float*)d_in[1];
    const float* w_o    = (const float*)d_in[2];
    const float* qnw    = (const float*)d_in[3];
    const float* knw    = (const float*)d_in[4];
    const float* cosT   = (const float*)d_in[5];
    const float* sinT   = (const float*)d_in[6];
    const int* positions = (const int*)d_in[9];
    float* out = (float*)d_out;

    float *qkv, *scores, *att, *hs_r, *wqkv_r, *wo_r, *vt;
    cudaGetSymbolAddress((void**)&qkv,    g_qkv);
    cudaGetSymbolAddress((void**)&scores, g_scores);
    cudaGetSymbolAddress((void**)&att,    g_att);
    cudaGetSymbolAddress((void**)&hs_r,   g_hs_r);
    cudaGetSymbolAddress((void**)&wqkv_r, g_wqkv_r);
    cudaGetSymbolAddress((void**)&wo_r,   g_wo_r);
    cudaGetSymbolAddress((void**)&vt,     g_vt);

    const int SMEM = 3 * 2 * 128 * 8 * 16;  // 96 KB
    cudaFuncSetAttribute(mma_gemm<false, false, true >, cudaFuncAttributeMaxDynamicSharedMemorySize, SMEM);
    cudaFuncSetAttribute(mma_gemm<true,  false, false>, cudaFuncAttributeMaxDynamicSharedMemorySize, SMEM);
    cudaFuncSetAttribute(mma_gemm<false, true,  true >, cudaFuncAttributeMaxDynamicSharedMemorySize, SMEM);
    cudaFuncSetAttribute(mma_gemm<false, false, false>, cudaFuncAttributeMaxDynamicSharedMemorySize, SMEM);

    // 0) tf32-round raw operands
    round_copy<<<(SQ*HID/4 + 255)/256, 256>>>(hs, hs_r, SQ*HID/4);
    round_copy<<<(QKV_DIM*HID/4 + 255)/256, 256>>>(w_qkv, wqkv_r, QKV_DIM*HID/4);
    round_copy<<<(HID*NH*HD/4 + 255)/256, 256>>>(w_o, wo_r, HID*NH*HD/4);

    // 1) QKV projection
    mma_gemm<false, false, true><<<dim3(QKV_DIM/128, SQ/128, 1), 256, SMEM>>>(
        hs_r, wqkv_r, qkv, HID, HID, HID, QKV_DIM, 0, 0, 1, 0, 1.0f);

    // 2) RMSNorm + RoPE in-place
    norm_rope_kernel<<<dim3(SQ, NH + NKV), 128>>>(qnw, knw, cosT, sinT, positions);

    // 3) V transpose
    vt_kernel<<<dim3(SQ/32, NKV*HD/32), 256>>>();

    // 4) scores = Q @ K^T * SCALE (causal tile skip)
    mma_gemm<true, false, false><<<dim3(SQ/128, SQ/128, NH), 256, SMEM>>>(
        qkv, qkv + NH*HD, scores, HD, QKV_DIM, QKV_DIM, SQ,
        HD, HD, NH/NKV, (long long)SQ * SQ, ATT_SCALE);

    // 5) causal softmax
    softmax_kernel<<<dim3(SQ, NH), 256>>>();

    // 6) att = P @ V (causal-K bound)
    mma_gemm<false, true, true><<<dim3(HD/128, SQ/128, NH), 256, SMEM>>>(
        scores, vt, att, SQ, SQ, SQ, NH*HD,
        (long long)SQ * SQ, (long long)HD * SQ, NH/NKV, HD, 1.0f);

    // 7) output projection
    mma_gemm<false, false, false><<<dim3(HID/128, SQ/128, 1), 256, SMEM>>>(
        att, wo_r, out, NH*HD, NH*HD, NH*HD, HID, 0, 0, 1, 0, 1.0f);
}

// round 7
// speedup vs baseline: 1.5645x; 1.0271x over previous
#include <cuda_runtime.h>
#include <cstdint>

#define SQ   2048
#define HID  2560
#define NH   16
#define NKV  4
#define HD   128
#define QKV_DIM (NH*HD + 2*NKV*HD)   // 3072
#define EPS  1e-6f
#define ATT_SCALE 0.08838834764831845f  // 1/sqrt(128)
#define VOFF (NH*HD + NKV*HD)

// ---------------- scratch (device globals, no allocation) ----------------
__device__ float g_qkv[(size_t)SQ * QKV_DIM];
__device__ float g_att[(size_t)SQ * NH * HD];
__device__ float g_hs_r[(size_t)SQ * HID];
__device__ float g_wqkv_r[(size_t)QKV_DIM * HID];
__device__ float g_wo_r[(size_t)HID * NH * HD];
__device__ float g_vt[(size_t)NKV * HD * SQ];

__device__ __forceinline__ uint32_t f2tf32(float x) {
    uint32_t u;
    asm("cvt.rna.tf32.f32 %0, %1;" : "=r"(u) : "f"(x));
    return u;
}
__device__ __forceinline__ float roundtf(float x) { return __uint_as_float(f2tf32(x)); }

__device__ __forceinline__ void mma_tf32(float* d, const uint32_t* a, const uint32_t* b) {
    asm volatile(
        "mma.sync.aligned.m16n8k8.row.col.f32.tf32.tf32.f32 "
        "{%0,%1,%2,%3}, {%4,%5,%6,%7}, {%8,%9}, {%0,%1,%2,%3};\n"
        : "+f"(d[0]), "+f"(d[1]), "+f"(d[2]), "+f"(d[3])
        : "r"(a[0]), "r"(a[1]), "r"(a[2]), "r"(a[3]), "r"(b[0]), "r"(b[1]));
}

__device__ __forceinline__ void ldmx4(uint32_t* r, uint32_t addr) {
    asm volatile("ldmatrix.sync.aligned.m8n8.x4.shared.b16 {%0,%1,%2,%3}, [%4];"
        : "=r"(r[0]), "=r"(r[1]), "=r"(r[2]), "=r"(r[3]) : "r"(addr));
}

__device__ __forceinline__ void cpasync(uint32_t d, const float* s) {
    asm volatile("cp.async.cg.shared.global [%0], [%1], 16;\n" :: "r"(d), "l"(s));
}

// ---------------- tf32 tensor-core GEMM (R6 engine: QKV + O-proj) ----------------
template<bool ROUND>
__global__ void __launch_bounds__(256, 2) mma_gemm(
    const float* __restrict__ A, const float* __restrict__ B, float* __restrict__ C,
    int K, int lda, int ldb, int ldc, float alpha)
{
    const int bx = blockIdx.x, by = blockIdx.y;

    extern __shared__ float4 dynsmem[];
    const uint32_t sbase = (uint32_t)__cvta_generic_to_shared(dynsmem);

    const int t    = threadIdx.x;
    const int lane = t & 31, wid = t >> 5;
    const int wm   = (wid & 1) * 64;
    const int wn   = (wid >> 1) * 32;
    const int m0   = by * 128, n0 = bx * 128;
    const int grp  = lane >> 2, tid4 = lane & 3;

    const int l8    = lane & 7;
    const int aoff8 = ((lane >> 3) & 1) * 8;
    const int ags   = (lane >> 4) & 1;
    const int boff8 = ((lane >> 4) & 1) * 8;
    const int bgs   = (lane >> 3) & 1;
    uint32_t arow[4], brow[2];
    #pragma unroll
    for (int mt = 0; mt < 4; mt++) arow[mt] = (uint32_t)(wm + mt * 16 + aoff8 + l8) * 128u;
    #pragma unroll
    for (int pr = 0; pr < 2; pr++) brow[pr] = (uint32_t)(wn + pr * 16 + boff8 + l8) * 128u;

    const int lrow = t >> 1;
    const int cb   = (t & 1) * 4;
    const int x7   = lrow & 7;
    const float* Aptr = A + (long long)(m0 + lrow) * lda;
    const float* Bptr = B + (long long)(n0 + lrow) * ldb;

    float acc[4][4][4];
    #pragma unroll
    for (int i = 0; i < 4; i++)
        #pragma unroll
        for (int j = 0; j < 4; j++)
            #pragma unroll
            for (int r = 0; r < 4; r++) acc[i][j][r] = 0.f;

    const int nK = K >> 5;

    auto issue = [&](int st, int k0) {
        const uint32_t ab = sbase + st * 16384u + (uint32_t)lrow * 128u;
        const uint32_t bb = sbase + 49152u + st * 16384u + (uint32_t)lrow * 128u;
        #pragma unroll
        for (int c = 0; c < 4; c++)
            cpasync(ab + (uint32_t)(((cb + c) ^ x7) << 4), Aptr + k0 + (cb + c) * 4);
        #pragma unroll
        for (int c = 0; c < 4; c++)
            cpasync(bb + (uint32_t)(((cb + c) ^ x7) << 4), Bptr + k0 + (cb + c) * 4);
    };

    issue(0, 0);
    asm volatile("cp.async.commit_group;\n");
    issue(1, 32);
    asm volatile("cp.async.commit_group;\n");

    for (int kt = 0; kt < nK; kt++) {
        asm volatile("cp.async.wait_group 1;\n");
        __syncthreads();

        const int st = kt - (kt / 3) * 3;
        const uint32_t sA = sbase + st * 16384u;
        const uint32_t sB = sbase + 49152u + st * 16384u;

        #pragma unroll
        for (int j = 0; j < 4; j++) {
            const uint32_t ga = (uint32_t)(((2 * j + ags) ^ l8) << 4);
            const uint32_t gb = (uint32_t)(((2 * j + bgs) ^ l8) << 4);
            uint32_t af[4][4], bq[2][4];
            #pragma unroll
            for (int mt = 0; mt < 4; mt++) ldmx4(af[mt], sA + arow[mt] + ga);
            ldmx4(bq[0], sB + brow[0] + gb);
            ldmx4(bq[1], sB + brow[1] + gb);
            #pragma unroll
            for (int mt = 0; mt < 4; mt++) {
                mma_tf32(acc[mt][0], af[mt], &bq[0][0]);
                mma_tf32(acc[mt][1], af[mt], &bq[0][2]);
                mma_tf32(acc[mt][2], af[mt], &bq[1][0]);
                mma_tf32(acc[mt][3], af[mt], &bq[1][2]);
            }
        }

        if (kt + 2 < nK) issue((kt + 2) - ((kt + 2) / 3) * 3, (kt + 2) << 5);
        asm volatile("cp.async.commit_group;\n");
    }

    #pragma unroll
    for (int mt = 0; mt < 4; mt++) {
        #pragma unroll
        for (int nt = 0; nt < 4; nt++) {
            const int r0 = m0 + wm + mt * 16 + grp;
            const int col = n0 + wn + nt * 8 + tid4 * 2;
            float2 lo, hi;
            lo.x = acc[mt][nt][0] * alpha; lo.y = acc[mt][nt][1] * alpha;
            hi.x = acc[mt][nt][2] * alpha; hi.y = acc[mt][nt][3] * alpha;
            if (ROUND) {
                lo.x = roundtf(lo.x); lo.y = roundtf(lo.y);
                hi.x = roundtf(hi.x); hi.y = roundtf(hi.y);
            }
            *(float2*)(C + (long long)r0 * ldc + col)       = lo;
            *(float2*)(C + (long long)(r0 + 8) * ldc + col) = hi;
        }
    }
}

// ---------------- fused flash attention ----------------
// grid (NH, 16 q-tiles), 256 threads. CTA: q-tile 128 rows of head h.
// SMEM: Q [4kc][128][32f] 64KB | K 2st x [4kc][64][32f] 64KB |
//       Vt 2st x [2kc][128][32f] 64KB | P [2kc][128][32f] 32KB  = 224KB
__global__ void __launch_bounds__(256, 1) flash_kernel()
{
    extern __shared__ char fsm[];
    const uint32_t sb = (uint32_t)__cvta_generic_to_shared(fsm);
    const uint32_t Qb = sb;
    const uint32_t Kb = sb + 65536u;
    const uint32_t Vb = sb + 131072u;
    const uint32_t Pb = sb + 196608u;

    const int h  = blockIdx.x;
    const int yy = blockIdx.y;
    const int qt = (yy < 8) ? (15 - yy) : (yy - 8);   // heavy tiles first
    const int hkv = h >> 2;

    const int t = threadIdx.x, lane = t & 31, wid = t >> 5;
    const int grp = lane >> 2, tid4 = lane & 3;
    const int l8 = lane & 7;
    const int aoff8 = ((lane >> 3) & 1) * 8;
    const int ags   = (lane >> 4) & 1;
    const int boff8 = ((lane >> 4) & 1) * 8;
    const int bgs   = (lane >> 3) & 1;

    const float* Qg  = g_qkv + h * HD;
    const float* Kg  = g_qkv + NH * HD + hkv * HD;
    const float* Vtg = g_vt + (size_t)hkv * HD * SQ;

    // ---- load Q tile (once) ----
    {
        const int r = t >> 1, cb = (t & 1) * 4, x7 = r & 7;
        const float* src = Qg + (size_t)(qt * 128 + r) * QKV_DIM;
        #pragma unroll
        for (int kc = 0; kc < 4; kc++)
            #pragma unroll
            for (int c = 0; c < 4; c++)
                cpasync(Qb + kc * 16384u + (uint32_t)r * 128u +
                        ((uint32_t)((cb + c) ^ x7) << 4),
                        src + kc * 32 + (cb + c) * 4);
    }

    const int T = 2 * qt + 2;
    const int kr = t & 63, kkc = t >> 6;
    const int vd = t >> 1, vh = t & 1;
    const int kx7 = kr & 7, vx7 = vd & 7;

    auto issueKV = [&](int st, int kv0) {
        const uint32_t Ks = Kb + (uint32_t)st * 32768u;
        const float* ksrc = Kg + (size_t)(kv0 + kr) * QKV_DIM + kkc * 32;
        #pragma unroll
        for (int g = 0; g < 8; g++)
            cpasync(Ks + kkc * 8192u + (uint32_t)kr * 128u + ((uint32_t)(g ^ kx7) << 4),
                    ksrc + g * 4);
        const uint32_t Vs = Vb + (uint32_t)st * 32768u;
        const float* vsrc = Vtg + (size_t)vd * SQ + kv0 + vh * 32;
        #pragma unroll
        for (int g = 0; g < 8; g++)
            cpasync(Vs + vh * 16384u + (uint32_t)vd * 128u + ((uint32_t)(g ^ vx7) << 4),
                    vsrc + g * 4);
    };
    issueKV(0, 0);
    asm volatile("cp.async.commit_group;\n");

    const uint32_t aQrow = (uint32_t)(wid * 16 + aoff8 + l8) * 128u;
    uint32_t bKrow[4], bVrow[8];
    #pragma unroll
    for (int pr = 0; pr < 4; pr++) bKrow[pr] = (uint32_t)(pr * 16 + boff8 + l8) * 128u;
    #pragma unroll
    for (int pr = 0; pr < 8; pr++) bVrow[pr] = (uint32_t)(pr * 16 + boff8 + l8) * 128u;

    float m0 = -1e30f, m1 = -1e30f, l0 = 0.f, l1 = 0.f;
    float O[16][4];
    #pragma unroll
    for (int i = 0; i < 16; i++)
        #pragma unroll
        for (int e = 0; e < 4; e++) O[i][e] = 0.f;

    const int q0 = qt * 128 + wid * 16 + grp;

    for (int tl = 0; tl < T; tl++) {
        asm volatile("cp.async.wait_group 0;\n");
        __syncthreads();
        if (tl + 1 < T) issueKV((tl + 1) & 1, (tl + 1) * 64);
        asm volatile("cp.async.commit_group;\n");

        const uint32_t Ks = Kb + (uint32_t)(tl & 1) * 32768u;
        const uint32_t Vs = Vb + (uint32_t)(tl & 1) * 32768u;
        const int kv0 = tl * 64;

        // ---- S = Q K^T (warp: 16q x 64kv, K-loop 128) ----
        float s[8][4];
        #pragma unroll
        for (int i = 0; i < 8; i++)
            #pragma unroll
            for (int e = 0; e < 4; e++) s[i][e] = 0.f;

        #pragma unroll
        for (int j = 0; j < 16; j++) {
            const uint32_t gA = (uint32_t)(((2 * (j & 3) + ags) ^ l8) << 4);
            const uint32_t gB = (uint32_t)(((2 * (j & 3) + bgs) ^ l8) << 4);
            uint32_t af[4], bq[4][4];
            ldmx4(af, Qb + (j >> 2) * 16384u + aQrow + gA);
            #pragma unroll
            for (int pr = 0; pr < 4; pr++)
                ldmx4(bq[pr], Ks + (j >> 2) * 8192u + bKrow[pr] + gB);
            #pragma unroll
            for (int nt = 0; nt < 8; nt++)
                mma_tf32(s[nt], af, &bq[nt >> 1][(nt & 1) * 2]);
        }

        // ---- scale + causal mask + online softmax ----
        const bool msk = (tl >= 2 * qt);
        float rm0 = -1e30f, rm1 = -1e30f;
        #pragma unroll
        for (int nt = 0; nt < 8; nt++) {
            const int c0 = kv0 + nt * 8 + 2 * tid4;
            float v0 = s[nt][0] * ATT_SCALE, v1 = s[nt][1] * ATT_SCALE;
            float v2 = s[nt][2] * ATT_SCALE, v3 = s[nt][3] * ATT_SCALE;
            if (msk) {
                if (c0     > q0)     v0 = -1e30f;
                if (c0 + 1 > q0)     v1 = -1e30f;
                if (c0     > q0 + 8) v2 = -1e30f;
                if (c0 + 1 > q0 + 8) v3 = -1e30f;
            }
            s[nt][0] = v0; s[nt][1] = v1; s[nt][2] = v2; s[nt][3] = v3;
            rm0 = fmaxf(rm0, fmaxf(v0, v1));
            rm1 = fmaxf(rm1, fmaxf(v2, v3));
        }
        rm0 = fmaxf(rm0, __shfl_xor_sync(0xffffffffu, rm0, 1));
        rm0 = fmaxf(rm0, __shfl_xor_sync(0xffffffffu, rm0, 2));
        rm1 = fmaxf(rm1, __shfl_xor_sync(0xffffffffu, rm1, 1));
        rm1 = fmaxf(rm1, __shfl_xor_sync(0xffffffffu, rm1, 2));

        const float mn0 = fmaxf(m0, rm0), mn1 = fmaxf(m1, rm1);
        const float sc0 = __expf(m0 - mn0), sc1 = __expf(m1 - mn1);
        m0 = mn0; m1 = mn1;

        float sum0 = 0.f, sum1 = 0.f;
        #pragma unroll
        for (int nt = 0; nt < 8; nt++) {
            s[nt][0] = __expf(s[nt][0] - m0);
            s[nt][1] = __expf(s[nt][1] - m0);
            s[nt][2] = __expf(s[nt][2] - m1);
            s[nt][3] = __expf(s[nt][3] - m1);
            sum0 += s[nt][0] + s[nt][1];
            sum1 += s[nt][2] + s[nt][3];
        }
        sum0 += __shfl_xor_sync(0xffffffffu, sum0, 1);
        sum0 += __shfl_xor_sync(0xffffffffu, sum0, 2);
        sum1 += __shfl_xor_sync(0xffffffffu, sum1, 1);
        sum1 += __shfl_xor_sync(0xffffffffu, sum1, 2);
        l0 = l0 * sc0 + sum0;
        l1 = l1 * sc1 + sum1;

        #pragma unroll
        for (int nt = 0; nt < 16; nt++) {
            O[nt][0] *= sc0; O[nt][1] *= sc0;
            O[nt][2] *= sc1; O[nt][3] *= sc1;
        }

        // ---- write P to SMEM (chunked swizzled layout for ldmatrix A) ----
        {
            const int r0w = wid * 16 + grp;
            const int r1w = r0w + 8;
            const int fl  = (2 * tid4) & 3;
            #pragma unroll
            for (int nt = 0; nt < 8; nt++) {
                const int kc = nt >> 2;
                const int gg = ((nt & 3) * 8 + 2 * tid4) >> 2;
                const uint32_t a0 = Pb + kc * 16384u + (uint32_t)r0w * 128u +
                                    ((uint32_t)(gg ^ (r0w & 7)) << 4) + fl * 4;
                const uint32_t a1 = Pb + kc * 16384u + (uint32_t)r1w * 128u +
                                    ((uint32_t)(gg ^ (r1w & 7)) << 4) + fl * 4;
                asm volatile("st.shared.v2.f32 [%0], {%1,%2};"
                             :: "r"(a0), "f"(roundtf(s[nt][0])), "f"(roundtf(s[nt][1])));
                asm volatile("st.shared.v2.f32 [%0], {%1,%2};"
                             :: "r"(a1), "f"(roundtf(s[nt][2])), "f"(roundtf(s[nt][3])));
            }
        }
        __syncthreads();

        // ---- O += P @ V (warp: 16q x 128d, K-loop 64 kv) ----
        #pragma unroll
        for (int j = 0; j < 8; j++) {
            const uint32_t gA = (uint32_t)(((2 * (j & 3) + ags) ^ l8) << 4);
            const uint32_t gB = (uint32_t)(((2 * (j & 3) + bgs) ^ l8) << 4);
            uint32_t af[4], bq[8][4];
            ldmx4(af, Pb + (j >> 2) * 16384u + aQrow + gA);
            #pragma unroll
            for (int pr = 0; pr < 8; pr++)
                ldmx4(bq[pr], Vs + (j >> 2) * 16384u + bVrow[pr] + gB);
            #pragma unroll
            for (int nt = 0; nt < 16; nt++)
                mma_tf32(O[nt], af, &bq[nt >> 1][(nt & 1) * 2]);
        }
    }

    // ---- epilogue: normalize, round, store ----
    const float inv0 = 1.f / l0, inv1 = 1.f / l1;
    const int row0 = qt * 128 + wid * 16 + grp;
    float* o0 = g_att + (size_t)row0 * (NH * HD) + h * HD;
    float* o1 = o0 + (size_t)8 * (NH * HD);
    #pragma unroll
    for (int nt = 0; nt < 16; nt++) {
        const int col = nt * 8 + 2 * tid4;
        float2 a, b;
        a.x = roundtf(O[nt][0] * inv0); a.y = roundtf(O[nt][1] * inv0);
        b.x = roundtf(O[nt][2] * inv1); b.y = roundtf(O[nt][3] * inv1);
        *(float2*)(o0 + col) = a;
        *(float2*)(o1 + col) = b;
    }
}

// ---------------- tf32 round-copy ----------------
__global__ void __launch_bounds__(256) round_copy(const float* __restrict__ src,
                                                 float* __restrict__ dst, int n4)
{
    int i = blockIdx.x * 256 + threadIdx.x;
    if (i < n4) {
        float4 v = ((const float4*)src)[i];
        v.x = roundtf(v.x); v.y = roundtf(v.y);
        v.z = roundtf(v.z); v.w = roundtf(v.w);
        ((float4*)dst)[i] = v;
    }
}

// ---------------- V transpose ----------------
__global__ void __launch_bounds__(256) vt_kernel()
{
    __shared__ float tile[32][33];
    const int s0 = blockIdx.x * 32, d0 = blockIdx.y * 32;
    const int tx = threadIdx.x & 31, ty = threadIdx.x >> 5;
    #pragma unroll
    for (int r = ty; r < 32; r += 8)
        tile[r][tx] = g_qkv[(long long)(s0 + r) * QKV_DIM + VOFF + d0 + tx];
    __syncthreads();
    #pragma unroll
    for (int r = ty; r < 32; r += 8)
        g_vt[(long long)(d0 + r) * SQ + s0 + tx] = tile[tx][r];
}

// ---------------- fused RMSNorm + RoPE ----------------
__global__ void __launch_bounds__(128) norm_rope_kernel(
    const float* __restrict__ qw, const float* __restrict__ kw,
    const float* __restrict__ cosT, const float* __restrict__ sinT,
    const int* __restrict__ positions)
{
    const int tok = blockIdx.x;
    const int hh  = blockIdx.y;
    const int d   = threadIdx.x;

    float* ptr;
    const float* w;
    if (hh < NH) { ptr = g_qkv + (long long)tok * QKV_DIM + hh * HD;            w = qw; }
    else         { ptr = g_qkv + (long long)tok * QKV_DIM + NH*HD + (hh-NH)*HD; w = kw; }

    __shared__ float x[HD];
    __shared__ float red[4];

    float v = ptr[d];
    float ss = v * v;
    #pragma unroll
    for (int o = 16; o > 0; o >>= 1) ss += __shfl_xor_sync(0xffffffffu, ss, o);
    if ((d & 31) == 0) red[d >> 5] = ss;
    __syncthreads();
    float tot = red[0] + red[1] + red[2] + red[3];
    float r = rsqrtf(tot * (1.0f / HD) + EPS);
    x[d] = v * r * w[d];
    __syncthreads();

    const int pos = positions[tok];
    const int p = d >> 1;
    const float c = cosT[pos * (HD/2) + p];
    const float s = sinT[pos * (HD/2) + p];
    float out;
    if ((d & 1) == 0) out = x[d] * c - x[d + 1] * s;
    else              out = x[d - 1] * s + x[d] * c;
    ptr[d] = roundtf(out);
}

// ---------------- launch ----------------
extern "C" void kernel_launch(void* const* d_in, const int* in_sizes, int n_in,
                              void* d_out, int out_size)
{
    const float* hs     = (const float*)d_in[0];
    const float* w_qkv  = (const float*)d_in[1];
    const float* w_o    = (const float*)d_in[2];
    const float* qnw    = (const float*)d_in[3];
    const float* knw    = (const float*)d_in[4];
    const float* cosT   = (const float*)d_in[5];
    const float* sinT   = (const float*)d_in[6];
    const int* positions = (const int*)d_in[9];
    float* out = (float*)d_out;

    float *qkv, *att, *hs_r, *wqkv_r, *wo_r, *vt;
    cudaGetSymbolAddress((void**)&qkv,    g_qkv);
    cudaGetSymbolAddress((void**)&att,    g_att);
    cudaGetSymbolAddress((void**)&hs_r,   g_hs_r);
    cudaGetSymbolAddress((void**)&wqkv_r, g_wqkv_r);
    cudaGetSymbolAddress((void**)&wo_r,   g_wo_r);
    cudaGetSymbolAddress((void**)&vt,     g_vt);

    const int GSMEM = 3 * 2 * 128 * 8 * 16;  // 96 KB
    const int FSMEM = 229376;                // 224 KB
    cudaFuncSetAttribute(mma_gemm<true >, cudaFuncAttributeMaxDynamicSharedMemorySize, GSMEM);
    cudaFuncSetAttribute(mma_gemm<false>, cudaFuncAttributeMaxDynamicSharedMemorySize, GSMEM);
    cudaFuncSetAttribute(flash_kernel,    cudaFuncAttributeMaxDynamicSharedMemorySize, FSMEM);

    // 0) tf32-round raw operands
    round_copy<<<(SQ*HID/4 + 255)/256, 256>>>(hs, hs_r, SQ*HID/4);
    round_copy<<<(QKV_DIM*HID/4 + 255)/256, 256>>>(w_qkv, wqkv_r, QKV_DIM*HID/4);
    round_copy<<<(HID*NH*HD/4 + 255)/256, 256>>>(w_o, wo_r, HID*NH*HD/4);

    // 1) QKV projection (epilogue rounds q,k,v to tf32)
    mma_gemm<true><<<dim3(QKV_DIM/128, SQ/128, 1), 256, GSMEM>>>(
        hs_r, wqkv_r, qkv, HID, HID, HID, QKV_DIM, 1.0f);

    // 2) RMSNorm + RoPE in-place (rounds q,k)
    norm_rope_kernel<<<dim3(SQ, NH + NKV), 128>>>(qnw, knw, cosT, sinT, positions);

    // 3) V transpose -> g_vt [NKV*HD][SQ]
    vt_kernel<<<dim3(SQ/32, NKV*HD/32), 256>>>();

    // 4) fused flash attention -> g_att
    flash_kernel<<<dim3(NH, 16), 256, FSMEM>>>();

    // 5) output projection
    mma_gemm<false><<<dim3(HID/128, SQ/128, 1), 256, GSMEM>>>(
        att, wo_r, out, NH*HD, NH*HD, NH*HD, HID, 1.0f);
}

// round 8
// speedup vs baseline: 2.8095x; 1.7958x over previous
#include <cuda_runtime.h>
#include <cuda_fp16.h>
#include <cstdint>

#define SQ   2048
#define HID  2560
#define NH   16
#define NKV  4
#define HD   128
#define QKV_DIM (NH*HD + 2*NKV*HD)   // 3072
#define EPS  1e-6f
#define ATT_SCALE 0.08838834764831845f  // 1/sqrt(128)
#define VOFF (NH*HD + NKV*HD)

// ---------------- scratch (device globals, no allocation) ----------------
__device__ __half g_qkv[(size_t)SQ * QKV_DIM];       // 12.6 MB
__device__ __half g_att[(size_t)SQ * NH * HD];       // 8 MB
__device__ __half g_hs_h[(size_t)SQ * HID];
__device__ __half g_wqkv_h[(size_t)QKV_DIM * HID];
__device__ __half g_wo_h[(size_t)HID * NH * HD];
__device__ __half g_vt[(size_t)NKV * HD * SQ];       // V transposed [d][s]

__device__ __forceinline__ void mma_f16(float* d, const uint32_t* a, const uint32_t* b) {
    asm volatile(
        "mma.sync.aligned.m16n8k16.row.col.f32.f16.f16.f32 "
        "{%0,%1,%2,%3}, {%4,%5,%6,%7}, {%8,%9}, {%0,%1,%2,%3};\n"
        : "+f"(d[0]), "+f"(d[1]), "+f"(d[2]), "+f"(d[3])
        : "r"(a[0]), "r"(a[1]), "r"(a[2]), "r"(a[3]), "r"(b[0]), "r"(b[1]));
}

__device__ __forceinline__ void ldmx4(uint32_t* r, uint32_t addr) {
    asm volatile("ldmatrix.sync.aligned.m8n8.x4.shared.b16 {%0,%1,%2,%3}, [%4];"
        : "=r"(r[0]), "=r"(r[1]), "=r"(r[2]), "=r"(r[3]) : "r"(addr));
}

__device__ __forceinline__ void cpasync(uint32_t d, const void* s) {
    asm volatile("cp.async.cg.shared.global [%0], [%1], 16;\n" :: "r"(d), "l"(s));
}

__device__ __forceinline__ uint32_t h2u(__half2 h) {
    return *reinterpret_cast<uint32_t*>(&h);
}

// ---------------- fp16 tensor-core GEMM ----------------
// C[m,n] = alpha * sum_k A[m,k] * B[n,k]  (row-major NT), fp32 accumulate.
// 128x128 CTA tile, 256 thr (8 warps, 2Mx4N of 64x32), K chunks of 64 (128B/row),
// 3-stage cp.async, ldmatrix fragments, m16n8k16.
template<bool OUTF32>
__global__ void __launch_bounds__(256, 2) mma_gemm(
    const __half* __restrict__ A, const __half* __restrict__ B, void* __restrict__ Cv,
    int K, int lda, int ldb, int ldc, float alpha)
{
    const int bx = blockIdx.x, by = blockIdx.y;

    extern __shared__ char smem[];
    const uint32_t sbase = (uint32_t)__cvta_generic_to_shared(smem);
    // A stages: sbase + st*16384 ; B stages: sbase + 49152 + st*16384

    const int t    = threadIdx.x;
    const int lane = t & 31, wid = t >> 5;
    const int wm   = (wid & 1) * 64;
    const int wn   = (wid >> 1) * 32;
    const int m0   = by * 128, n0 = bx * 128;
    const int grp  = lane >> 2, tid4 = lane & 3;

    const int l8    = lane & 7;
    const int aoff8 = ((lane >> 3) & 1) * 8;
    const int ags   = (lane >> 4) & 1;
    const int boff8 = ((lane >> 4) & 1) * 8;
    const int bgs   = (lane >> 3) & 1;
    uint32_t arow[4], brow[2];
    #pragma unroll
    for (int mt = 0; mt < 4; mt++) arow[mt] = (uint32_t)(wm + mt * 16 + aoff8 + l8) * 128u;
    #pragma unroll
    for (int pr = 0; pr < 2; pr++) brow[pr] = (uint32_t)(wn + pr * 16 + boff8 + l8) * 128u;

    const int lrow = t >> 1;
    const int cb   = (t & 1) * 4;
    const int x7   = lrow & 7;
    const __half* Aptr = A + (long long)(m0 + lrow) * lda;
    const __half* Bptr = B + (long long)(n0 + lrow) * ldb;

    float acc[4][4][4];
    #pragma unroll
    for (int i = 0; i < 4; i++)
        #pragma unroll
        for (int j = 0; j < 4; j++)
            #pragma unroll
            for (int r = 0; r < 4; r++) acc[i][j][r] = 0.f;

    const int nK = K >> 6;   // chunks of 64 halves

    auto issue = [&](int st, int k0) {
        const uint32_t ab = sbase + st * 16384u + (uint32_t)lrow * 128u;
        const uint32_t bb = sbase + 49152u + st * 16384u + (uint32_t)lrow * 128u;
        #pragma unroll
        for (int c = 0; c < 4; c++)
            cpasync(ab + (uint32_t)(((cb + c) ^ x7) << 4), Aptr + k0 + (cb + c) * 8);
        #pragma unroll
        for (int c = 0; c < 4; c++)
            cpasync(bb + (uint32_t)(((cb + c) ^ x7) << 4), Bptr + k0 + (cb + c) * 8);
    };

    issue(0, 0);
    asm volatile("cp.async.commit_group;\n");
    issue(1, 64);
    asm volatile("cp.async.commit_group;\n");

    for (int kt = 0; kt < nK; kt++) {
        asm volatile("cp.async.wait_group 1;\n");
        __syncthreads();

        const int st = kt - (kt / 3) * 3;
        const uint32_t sA = sbase + st * 16384u;
        const uint32_t sB = sbase + 49152u + st * 16384u;

        #pragma unroll
        for (int j = 0; j < 4; j++) {      // 4 k16-steps per 64-chunk
            const uint32_t ga = (uint32_t)(((2 * j + ags) ^ l8) << 4);
            const uint32_t gb = (uint32_t)(((2 * j + bgs) ^ l8) << 4);
            uint32_t af[4][4], bq[2][4];
            #pragma unroll
            for (int mt = 0; mt < 4; mt++) ldmx4(af[mt], sA + arow[mt] + ga);
            ldmx4(bq[0], sB + brow[0] + gb);
            ldmx4(bq[1], sB + brow[1] + gb);
            #pragma unroll
            for (int mt = 0; mt < 4; mt++) {
                mma_f16(acc[mt][0], af[mt], &bq[0][0]);
                mma_f16(acc[mt][1], af[mt], &bq[0][2]);
                mma_f16(acc[mt][2], af[mt], &bq[1][0]);
                mma_f16(acc[mt][3], af[mt], &bq[1][2]);
            }
        }

        if (kt + 2 < nK) issue((kt + 2) - ((kt + 2) / 3) * 3, (kt + 2) << 6);
        asm volatile("cp.async.commit_group;\n");
    }

    #pragma unroll
    for (int mt = 0; mt < 4; mt++) {
        #pragma unroll
        for (int nt = 0; nt < 4; nt++) {
            const int r0 = m0 + wm + mt * 16 + grp;
            const int col = n0 + wn + nt * 8 + tid4 * 2;
            if (OUTF32) {
                float* C = (float*)Cv;
                float2 lo, hi;
                lo.x = acc[mt][nt][0] * alpha; lo.y = acc[mt][nt][1] * alpha;
                hi.x = acc[mt][nt][2] * alpha; hi.y = acc[mt][nt][3] * alpha;
                *(float2*)(C + (long long)r0 * ldc + col)       = lo;
                *(float2*)(C + (long long)(r0 + 8) * ldc + col) = hi;
            } else {
                __half* C = (__half*)Cv;
                __half2 lo = __floats2half2_rn(acc[mt][nt][0] * alpha, acc[mt][nt][1] * alpha);
                __half2 hi = __floats2half2_rn(acc[mt][nt][2] * alpha, acc[mt][nt][3] * alpha);
                *(__half2*)(C + (long long)r0 * ldc + col)       = lo;
                *(__half2*)(C + (long long)(r0 + 8) * ldc + col) = hi;
            }
        }
    }
}

// ---------------- fused flash attention (fp16 operands, fp32 softmax/accum) ----------------
// grid (NH, 16 q-tiles), 256 thr. SMEM: Q 32K | K 2x16K | Vt 2x16K | P 16K = 112KB.
__global__ void __launch_bounds__(256, 1) flash_kernel()
{
    extern __shared__ char fsm[];
    const uint32_t sb = (uint32_t)__cvta_generic_to_shared(fsm);
    const uint32_t Qb = sb;
    const uint32_t Kb = sb + 32768u;
    const uint32_t Vb = sb + 65536u;
    const uint32_t Pb = sb + 98304u;

    const int h  = blockIdx.x;
    const int yy = blockIdx.y;
    const int qt = (yy < 8) ? (15 - yy) : (yy - 8);   // heavy tiles first
    const int hkv = h >> 2;

    const int t = threadIdx.x, lane = t & 31, wid = t >> 5;
    const int grp = lane >> 2, tid4 = lane & 3;
    const int l8 = lane & 7;
    const int aoff8 = ((lane >> 3) & 1) * 8;
    const int ags   = (lane >> 4) & 1;
    const int boff8 = ((lane >> 4) & 1) * 8;
    const int bgs   = (lane >> 3) & 1;

    const __half* Qg  = g_qkv + h * HD;
    const __half* Kg  = g_qkv + NH * HD + hkv * HD;
    const __half* Vtg = g_vt + (size_t)hkv * HD * SQ;

    // ---- load Q tile once: 2 kc chunks [128][8 granules] ----
    {
        const int r = t >> 1, cb = (t & 1) * 4, x7 = r & 7;
        const __half* src = Qg + (size_t)(qt * 128 + r) * QKV_DIM;
        #pragma unroll
        for (int kc = 0; kc < 2; kc++)
            #pragma unroll
            for (int c = 0; c < 4; c++)
                cpasync(Qb + kc * 16384u + (uint32_t)r * 128u +
                        ((uint32_t)((cb + c) ^ x7) << 4),
                        src + kc * 64 + (cb + c) * 8);
    }

    const int T = 2 * qt + 2;
    const int kr = t & 63, kkc = (t >> 6) & 1, kgh = t >> 7;
    const int vd = t >> 1, vcb = (t & 1) * 4;
    const int kx7 = kr & 7, vx7 = vd & 7;

    auto issueKV = [&](int st, int kv0) {
        const uint32_t Ks = Kb + (uint32_t)st * 16384u;
        const __half* ksrc = Kg + (size_t)(kv0 + kr) * QKV_DIM + kkc * 64;
        #pragma unroll
        for (int c = 0; c < 4; c++) {
            const int g = kgh * 4 + c;
            cpasync(Ks + kkc * 8192u + (uint32_t)kr * 128u + ((uint32_t)(g ^ kx7) << 4),
                    ksrc + g * 8);
        }
        const uint32_t Vs = Vb + (uint32_t)st * 16384u;
        const __half* vsrc = Vtg + (size_t)vd * SQ + kv0;
        #pragma unroll
        for (int c = 0; c < 4; c++) {
            const int g = vcb + c;
            cpasync(Vs + (uint32_t)vd * 128u + ((uint32_t)(g ^ vx7) << 4),
                    vsrc + g * 8);
        }
    };
    issueKV(0, 0);
    asm volatile("cp.async.commit_group;\n");

    const uint32_t aQrow = (uint32_t)(wid * 16 + aoff8 + l8) * 128u;
    uint32_t bKrow[4], bVrow[8];
    #pragma unroll
    for (int pr = 0; pr < 4; pr++) bKrow[pr] = (uint32_t)(pr * 16 + boff8 + l8) * 128u;
    #pragma unroll
    for (int pr = 0; pr < 8; pr++) bVrow[pr] = (uint32_t)(pr * 16 + boff8 + l8) * 128u;

    float m0 = -1e30f, m1 = -1e30f, l0 = 0.f, l1 = 0.f;
    float O[16][4];
    #pragma unroll
    for (int i = 0; i < 16; i++)
        #pragma unroll
        for (int e = 0; e < 4; e++) O[i][e] = 0.f;

    const int q0 = qt * 128 + wid * 16 + grp;

    for (int tl = 0; tl < T; tl++) {
        asm volatile("cp.async.wait_group 0;\n");
        __syncthreads();
        if (tl + 1 < T) issueKV((tl + 1) & 1, (tl + 1) * 64);
        asm volatile("cp.async.commit_group;\n");

        const uint32_t Ks = Kb + (uint32_t)(tl & 1) * 16384u;
        const uint32_t Vs = Vb + (uint32_t)(tl & 1) * 16384u;
        const int kv0 = tl * 64;

        // ---- S = Q K^T (16q x 64kv, K=128 -> 8 k16-steps) ----
        float s[8][4];
        #pragma unroll
        for (int i = 0; i < 8; i++)
            #pragma unroll
            for (int e = 0; e < 4; e++) s[i][e] = 0.f;

        #pragma unroll
        for (int j = 0; j < 8; j++) {
            const int kc = j >> 2, jj = j & 3;
            const uint32_t gA = (uint32_t)(((2 * jj + ags) ^ l8) << 4);
            const uint32_t gB = (uint32_t)(((2 * jj + bgs) ^ l8) << 4);
            uint32_t af[4], bq[4][4];
            ldmx4(af, Qb + kc * 16384u + aQrow + gA);
            #pragma unroll
            for (int pr = 0; pr < 4; pr++)
                ldmx4(bq[pr], Ks + kc * 8192u + bKrow[pr] + gB);
            #pragma unroll
            for (int nt = 0; nt < 8; nt++)
                mma_f16(s[nt], af, &bq[nt >> 1][(nt & 1) * 2]);
        }

        // ---- scale + causal mask + online softmax (fp32) ----
        const bool msk = (tl >= 2 * qt);
        float rm0 = -1e30f, rm1 = -1e30f;
        #pragma unroll
        for (int nt = 0; nt < 8; nt++) {
            const int c0 = kv0 + nt * 8 + 2 * tid4;
            float v0 = s[nt][0] * ATT_SCALE, v1 = s[nt][1] * ATT_SCALE;
            float v2 = s[nt][2] * ATT_SCALE, v3 = s[nt][3] * ATT_SCALE;
            if (msk) {
                if (c0     > q0)     v0 = -1e30f;
                if (c0 + 1 > q0)     v1 = -1e30f;
                if (c0     > q0 + 8) v2 = -1e30f;
                if (c0 + 1 > q0 + 8) v3 = -1e30f;
            }
            s[nt][0] = v0; s[nt][1] = v1; s[nt][2] = v2; s[nt][3] = v3;
            rm0 = fmaxf(rm0, fmaxf(v0, v1));
            rm1 = fmaxf(rm1, fmaxf(v2, v3));
        }
        rm0 = fmaxf(rm0, __shfl_xor_sync(0xffffffffu, rm0, 1));
        rm0 = fmaxf(rm0, __shfl_xor_sync(0xffffffffu, rm0, 2));
        rm1 = fmaxf(rm1, __shfl_xor_sync(0xffffffffu, rm1, 1));
        rm1 = fmaxf(rm1, __shfl_xor_sync(0xffffffffu, rm1, 2));

        const float mn0 = fmaxf(m0, rm0), mn1 = fmaxf(m1, rm1);
        const float sc0 = __expf(m0 - mn0), sc1 = __expf(m1 - mn1);
        m0 = mn0; m1 = mn1;

        float sum0 = 0.f, sum1 = 0.f;
        #pragma unroll
        for (int nt = 0; nt < 8; nt++) {
            s[nt][0] = __expf(s[nt][0] - m0);
            s[nt][1] = __expf(s[nt][1] - m0);
            s[nt][2] = __expf(s[nt][2] - m1);
            s[nt][3] = __expf(s[nt][3] - m1);
            sum0 += s[nt][0] + s[nt][1];
            sum1 += s[nt][2] + s[nt][3];
        }
        sum0 += __shfl_xor_sync(0xffffffffu, sum0, 1);
        sum0 += __shfl_xor_sync(0xffffffffu, sum0, 2);
        sum1 += __shfl_xor_sync(0xffffffffu, sum1, 1);
        sum1 += __shfl_xor_sync(0xffffffffu, sum1, 2);
        l0 = l0 * sc0 + sum0;
        l1 = l1 * sc1 + sum1;

        #pragma unroll
        for (int nt = 0; nt < 16; nt++) {
            O[nt][0] *= sc0; O[nt][1] *= sc0;
            O[nt][2] *= sc1; O[nt][3] *= sc1;
        }

        // ---- write P (fp16) to SMEM in chunked swizzled layout ----
        {
            const int r0w = wid * 16 + grp, r1w = r0w + 8;
            #pragma unroll
            for (int nt = 0; nt < 8; nt++) {
                const uint32_t a0 = Pb + (uint32_t)r0w * 128u +
                                    ((uint32_t)(nt ^ (r0w & 7)) << 4) + tid4 * 4;
                const uint32_t a1 = Pb + (uint32_t)r1w * 128u +
                                    ((uint32_t)(nt ^ (r1w & 7)) << 4) + tid4 * 4;
                asm volatile("st.shared.b32 [%0], %1;"
                             :: "r"(a0), "r"(h2u(__floats2half2_rn(s[nt][0], s[nt][1]))));
                asm volatile("st.shared.b32 [%0], %1;"
                             :: "r"(a1), "r"(h2u(__floats2half2_rn(s[nt][2], s[nt][3]))));
            }
        }
        __syncthreads();

        // ---- O += P @ V (16q x 128d, K=64 kv -> 4 k16-steps) ----
        #pragma unroll
        for (int j = 0; j < 4; j++) {
            const uint32_t gA = (uint32_t)(((2 * j + ags) ^ l8) << 4);
            const uint32_t gB = (uint32_t)(((2 * j + bgs) ^ l8) << 4);
            uint32_t af[4], bq[8][4];
            ldmx4(af, Pb + aQrow + gA);
            #pragma unroll
            for (int pr = 0; pr < 8; pr++)
                ldmx4(bq[pr], Vs + bVrow[pr] + gB);
            #pragma unroll
            for (int nt = 0; nt < 16; nt++)
                mma_f16(O[nt], af, &bq[nt >> 1][(nt & 1) * 2]);
        }
    }

    // ---- epilogue: normalize, convert, store ----
    const float inv0 = 1.f / l0, inv1 = 1.f / l1;
    const int row0 = qt * 128 + wid * 16 + grp;
    __half* o0 = g_att + (size_t)row0 * (NH * HD) + h * HD;
    __half* o1 = o0 + (size_t)8 * (NH * HD);
    #pragma unroll
    for (int nt = 0; nt < 16; nt++) {
        const int col = nt * 8 + 2 * tid4;
        *(__half2*)(o0 + col) = __floats2half2_rn(O[nt][0] * inv0, O[nt][1] * inv0);
        *(__half2*)(o1 + col) = __floats2half2_rn(O[nt][2] * inv1, O[nt][3] * inv1);
    }
}

// ---------------- fp32 -> fp16 convert ----------------
__global__ void __launch_bounds__(256) cvt_half(const float* __restrict__ src,
                                               __half* __restrict__ dst, int n4)
{
    int i = blockIdx.x * 256 + threadIdx.x;
    if (i < n4) {
        float4 v = ((const float4*)src)[i];
        uint2 u;
        u.x = h2u(__floats2half2_rn(v.x, v.y));
        u.y = h2u(__floats2half2_rn(v.z, v.w));
        ((uint2*)dst)[i] = u;
    }
}

// ---------------- V transpose (half) ----------------
__global__ void __launch_bounds__(256) vt_kernel()
{
    __shared__ __half tile[32][40];
    const int s0 = blockIdx.x * 32, d0 = blockIdx.y * 32;
    const int tx = threadIdx.x & 31, ty = threadIdx.x >> 5;
    #pragma unroll
    for (int r = ty; r < 32; r += 8)
        tile[r][tx] = g_qkv[(long long)(s0 + r) * QKV_DIM + VOFF + d0 + tx];
    __syncthreads();
    #pragma unroll
    for (int r = ty; r < 32; r += 8)
        g_vt[(long long)(d0 + r) * SQ + s0 + tx] = tile[tx][r];
}

// ---------------- fused RMSNorm + RoPE (half in/out, fp32 math) ----------------
__global__ void __launch_bounds__(128) norm_rope_kernel(
    const float* __restrict__ qw, const float* __restrict__ kw,
    const float* __restrict__ cosT, const float* __restrict__ sinT,
    const int* __restrict__ positions)
{
    const int tok = blockIdx.x;
    const int hh  = blockIdx.y;
    const int d   = threadIdx.x;

    __half* ptr;
    const float* w;
    if (hh < NH) { ptr = g_qkv + (long long)tok * QKV_DIM + hh * HD;            w = qw; }
    else         { ptr = g_qkv + (long long)tok * QKV_DIM + NH*HD + (hh-NH)*HD; w = kw; }

    __shared__ float x[HD];
    __shared__ float red[4];

    float v = __half2float(ptr[d]);
    float ss = v * v;
    #pragma unroll
    for (int o = 16; o > 0; o >>= 1) ss += __shfl_xor_sync(0xffffffffu, ss, o);
    if ((d & 31) == 0) red[d >> 5] = ss;
    __syncthreads();
    float tot = red[0] + red[1] + red[2] + red[3];
    float r = rsqrtf(tot * (1.0f / HD) + EPS);
    x[d] = v * r * w[d];
    __syncthreads();

    const int pos = positions[tok];
    const int p = d >> 1;
    const float c = cosT[pos * (HD/2) + p];
    const float s = sinT[pos * (HD/2) + p];
    float out;
    if ((d & 1) == 0) out = x[d] * c - x[d + 1] * s;
    else              out = x[d - 1] * s + x[d] * c;
    ptr[d] = __float2half_rn(out);
}

// ---------------- launch ----------------
extern "C" void kernel_launch(void* const* d_in, const int* in_sizes, int n_in,
                              void* d_out, int out_size)
{
    const float* hs     = (const float*)d_in[0];
    const float* w_qkv  = (const float*)d_in[1];
    const float* w_o    = (const float*)d_in[2];
    const float* qnw    = (const float*)d_in[3];
    const float* knw    = (const float*)d_in[4];
    const float* cosT   = (const float*)d_in[5];
    const float* sinT   = (const float*)d_in[6];
    const int* positions = (const int*)d_in[9];
    float* out = (float*)d_out;

    __half *qkv, *att, *hs_h, *wqkv_h, *wo_h;
    cudaGetSymbolAddress((void**)&qkv,    g_qkv);
    cudaGetSymbolAddress((void**)&att,    g_att);
    cudaGetSymbolAddress((void**)&hs_h,   g_hs_h);
    cudaGetSymbolAddress((void**)&wqkv_h, g_wqkv_h);
    cudaGetSymbolAddress((void**)&wo_h,   g_wo_h);

    const int GSMEM = 3 * 2 * 16384;   // 96 KB
    const int FSMEM = 114688;          // 112 KB
    cudaFuncSetAttribute(mma_gemm<false>, cudaFuncAttributeMaxDynamicSharedMemorySize, GSMEM);
    cudaFuncSetAttribute(mma_gemm<true >, cudaFuncAttributeMaxDynamicSharedMemorySize, GSMEM);
    cudaFuncSetAttribute(flash_kernel,    cudaFuncAttributeMaxDynamicSharedMemorySize, FSMEM);

    // 0) convert operands to fp16
    cvt_half<<<(SQ*HID/4 + 255)/256, 256>>>(hs, hs_h, SQ*HID/4);
    cvt_half<<<(QKV_DIM*HID/4 + 255)/256, 256>>>(w_qkv, wqkv_h, QKV_DIM*HID/4);
    cvt_half<<<(HID*NH*HD/4 + 255)/256, 256>>>(w_o, wo_h, HID*NH*HD/4);

    // 1) QKV projection (half out)
    mma_gemm<false><<<dim3(QKV_DIM/128, SQ/128, 1), 256, GSMEM>>>(
        hs_h, wqkv_h, qkv, HID, HID, HID, QKV_DIM, 1.0f);

    // 2) RMSNorm + RoPE in-place on q,k
    norm_rope_kernel<<<dim3(SQ, NH + NKV), 128>>>(qnw, knw, cosT, sinT, positions);

    // 3) V transpose -> g_vt [NKV*HD][SQ]
    vt_kernel<<<dim3(SQ/32, NKV*HD/32), 256>>>();

    // 4) fused flash attention -> g_att (half)
    flash_kernel<<<dim3(NH, 16), 256, FSMEM>>>();

    // 5) output projection (float out)
    mma_gemm<true><<<dim3(HID/128, SQ/128, 1), 256, GSMEM>>>(
        att, wo_h, out, NH*HD, NH*HD, NH*HD, HID, 1.0f);
}